// round 16
// baseline (speedup 1.0000x reference)
#include <cuda_runtime.h>
#include <cuda_fp16.h>
#include <cstdint>

// ---------------- problem constants ----------------
#define HSZ   2048
#define BATCH 4096
#define KDIM  4096   // COMBINED
#define NDIM  8192   // 4H

// ---------------- fp16 scratch (device globals; no allocs) ----------------
__device__ __half g_A[(size_t)BATCH * KDIM];   // combined [B, C] fp16 (h_prev | x_t)
__device__ __half g_W[(size_t)NDIM * KDIM];    // weights, rows permuted n' = 4h + g
__device__ float  g_bias[NDIM];                // bias, permuted

__device__ __forceinline__ uint32_t smem_to_u32(const void* p) {
    uint32_t a;
    asm("{ .reg .u64 t; cvta.to.shared.u64 t, %1; cvt.u32.u64 %0, t; }" : "=r"(a) : "l"(p));
    return a;
}
// NON-volatile MMA: pure register op; lets ptxas interleave HMMA with ALU/LSU
__device__ __forceinline__ void mma16816(float* c, const uint32_t* a, const uint32_t* b) {
    asm("mma.sync.aligned.m16n8k16.row.col.f32.f16.f16.f32 "
        "{%0,%1,%2,%3}, {%4,%5,%6,%7}, {%8,%9}, {%0,%1,%2,%3};"
        : "+f"(c[0]), "+f"(c[1]), "+f"(c[2]), "+f"(c[3])
        : "r"(a[0]), "r"(a[1]), "r"(a[2]), "r"(a[3]), "r"(b[0]), "r"(b[1]));
}

// ---------------- pass 1: fused fp32 -> fp16 conversion (one kernel) ----------------
// Read-once fp32 sources use __ldcs (evict-first) so the fp16 write set — the
// GEMM's operand working set — stays resident in L2.
#define W4CNT (NDIM * KDIM / 4)      // 8388608 float4-groups for W
#define A4CNT (BATCH * KDIM / 4)     // 4194304 float4-groups for A

__global__ void conv_all_kernel(const float* __restrict__ x,  const float* __restrict__ h,
                                const float* __restrict__ Wf, const float* __restrict__ Wi,
                                const float* __restrict__ Wc, const float* __restrict__ Wo,
                                const float* __restrict__ bf, const float* __restrict__ bi,
                                const float* __restrict__ bc, const float* __restrict__ bo) {
    int i4 = blockIdx.x * blockDim.x + threadIdx.x;
    if (i4 < W4CNT) {
        size_t e = (size_t)i4 << 2;
        int n = (int)(e >> 12), k = (int)(e & 4095);    // n' = 4h + g (permuted row)
        int g = n & 3, hh = n >> 2;
        const float* src = (g == 0) ? Wf : (g == 1) ? Wi : (g == 2) ? Wc : Wo;
        float4 v = __ldcs((const float4*)(src + (size_t)hh * KDIM + k));
        __half2* dst = (__half2*)(g_W + e);
        dst[0] = __floats2half2_rn(v.x, v.y);
        dst[1] = __floats2half2_rn(v.z, v.w);
        if (i4 < NDIM) {                                // bias: first NDIM threads
            int gg = i4 & 3, hb = i4 >> 2;
            const float* sb = (gg == 0) ? bf : (gg == 1) ? bi : (gg == 2) ? bc : bo;
            g_bias[i4] = sb[hb];
        }
    } else {
        int j = i4 - W4CNT;                             // A part
        int e = j << 2;
        int m = e >> 12, k = e & 4095;
        float4 v = (k < HSZ) ? __ldcs((const float4*)(h + (size_t)m * HSZ + k))
                             : __ldcs((const float4*)(x + (size_t)m * HSZ + (k - HSZ)));
        __half2* dst = (__half2*)(g_A + e);
        dst[0] = __floats2half2_rn(v.x, v.y);
        dst[1] = __floats2half2_rn(v.z, v.w);
    }
}

// ---------------- pass 2: mma.sync GEMM (R9 loop, best measured) ----------------
// BM=BN=128, 128 threads (4 warps, 2x2 grid of 64x64 warp tiles), 2 CTAs/SM
#define BM 128
#define BN 128
#define KT 64                  // 4096 / 64
#define STAGE_A 16384          // 128 rows x 128B
#define STAGE_BYTES 32768      // A 16KB + B 16KB
#define SB2 (2 * STAGE_BYTES)
#define EPI_STRIDE 132         // floats per row (128 + 4 pad)
#define BIAS_OFF (3 * STAGE_BYTES)               // 98304
#define SMEM_TOTAL (BIAS_OFF + BN * 4)           // 98816 -> 2 CTAs/SM

#define NTHREADS 128

// hardware tanh (sm_75+): single MUFU op, max rel err ~2^-11
__device__ __forceinline__ float tanh_fast(float x) {
    float y; asm("tanh.approx.f32 %0, %1;" : "=f"(y) : "f"(x)); return y;
}
// sigmoid via tanh identity: 1 MUFU + 1 FMA (was EX2+RCP = 2 MUFU)
__device__ __forceinline__ float sigmoidf_(float x) {
    return fmaf(tanh_fast(0.5f * x), 0.5f, 0.5f);
}
__device__ __forceinline__ float tanhf_(float x) { return tanh_fast(x); }

// cp.async 16B with compile-time dst/src immediate offsets
#define CPI(da, sa, DI, SI) \
    asm volatile("cp.async.cg.shared.global [%0+%2], [%1+%3], 16;" \
                 :: "r"(da), "l"(sa), "n"(DI), "n"(SI) : "memory")

// ldmatrix x4 with compile-time immediate offset (row-tile stride 2048B)
#define LDSMI(rr, base, I) \
    asm volatile("ldmatrix.sync.aligned.m8n8.x4.shared.b16 {%0,%1,%2,%3}, [%4+%5];" \
                 : "=r"((rr)[0]), "=r"((rr)[1]), "=r"((rr)[2]), "=r"((rr)[3]) \
                 : "r"(base), "n"(I))

// prefetch one kstep's fragments: 2 address adds + 8 imm-offset ldsm
#define LDSM_FRAGS(dstA, dstB, sA, sB, kc) do {                    \
    uint32_t _aa = (sA) + a0 + ((((kc) + hi) ^ swz) << 4);         \
    uint32_t _bb = (sB) + b0 + ((((kc) + piece) ^ swz) << 4);      \
    LDSMI((dstA)[0], _aa, 0);    LDSMI((dstA)[1], _aa, 2048);      \
    LDSMI((dstA)[2], _aa, 4096); LDSMI((dstA)[3], _aa, 6144);      \
    LDSMI((dstB)[0], _bb, 0);    LDSMI((dstB)[1], _bb, 2048);      \
    LDSMI((dstB)[2], _bb, 4096); LDSMI((dstB)[3], _bb, 6144);      \
} while (0)

#define MMA_BURST(a, b) do {                                    \
    _Pragma("unroll")                                           \
    for (int _t = 0; _t < 4; _t++)                              \
        _Pragma("unroll")                                       \
        for (int _p = 0; _p < 4; _p++) {                        \
            mma16816(acc[_t][2 * _p],     (a)[_t], &(b)[_p][0]);\
            mma16816(acc[_t][2 * _p + 1], (a)[_t], &(b)[_p][2]);\
        }                                                       \
} while (0)

// one stage fill: 16 cp.async, all offsets immediate (16 rows * 8192B row-stride steps)
#define ISSUE_STAGE(saPtr, sbPtr, sOff) do {                                       \
    uint32_t _da = smem_u32 + (sOff) + dst0;                                       \
    uint32_t _db = _da + STAGE_A;                                                  \
    CPI(_da, (saPtr), 0, 0);            CPI(_da, (saPtr), 2048, 131072);           \
    CPI(_da, (saPtr), 4096, 262144);    CPI(_da, (saPtr), 6144, 393216);           \
    CPI(_da, (saPtr), 8192, 524288);    CPI(_da, (saPtr), 10240, 655360);          \
    CPI(_da, (saPtr), 12288, 786432);   CPI(_da, (saPtr), 14336, 917504);          \
    CPI(_db, (sbPtr), 0, 0);            CPI(_db, (sbPtr), 2048, 131072);           \
    CPI(_db, (sbPtr), 4096, 262144);    CPI(_db, (sbPtr), 6144, 393216);           \
    CPI(_db, (sbPtr), 8192, 524288);    CPI(_db, (sbPtr), 10240, 655360);          \
    CPI(_db, (sbPtr), 12288, 786432);   CPI(_db, (sbPtr), 14336, 917504);          \
    asm volatile("cp.async.commit_group;\n" ::: "memory");                         \
} while (0)

__global__ __launch_bounds__(NTHREADS, 2)
void lstm_gemm_kernel(const float* __restrict__ c_prev, float* __restrict__ out) {
    extern __shared__ char smem[];
    uint32_t smem_u32 = smem_to_u32(smem);
    float* smemf = (float*)smem;
    int tid = threadIdx.x;
    int lane = tid & 31, wid = tid >> 5;
    int wm = wid & 1, wn = wid >> 1;          // 2 x 2 warp grid, 64x64 warp tiles

    int mt = blockIdx.x & 31;                 // M-fastest: W panel stays hot in L2
    int nt = blockIdx.x >> 5;                 // 0..63
    int m0 = mt * BM, n0 = nt * BN;

    if (tid < BN / 4)
        ((float4*)(smem + BIAS_OFF))[tid] = ((const float4*)(g_bias + n0))[tid];

    // ---- cp.async addressing: incremental byte pointers, imm offsets inside stage ----
    uint32_t srcOff0b = (uint32_t)(((tid >> 3) * KDIM + (tid & 7) * 8) * 2);       // bytes
    uint32_t dst0     = (uint32_t)((tid >> 3) * 128 + (((tid & 7) ^ ((tid >> 3) & 7)) << 4));
    const char* srcA = (const char*)(g_A + (size_t)m0 * KDIM) + srcOff0b;
    const char* srcB = (const char*)(g_W + (size_t)n0 * KDIM) + srcOff0b;

    // ---- ldmatrix addressing ----
    uint32_t swz = (uint32_t)(lane & 7);
    uint32_t hi = (uint32_t)(lane >> 4);            // A k-half select
    uint32_t piece = (uint32_t)((lane >> 3) & 1);   // B k-half select
    uint32_t a0 = (uint32_t)((wm * 64 + (lane & 15)) * 128);
    uint32_t b0 = (uint32_t)((wn * 64 + (lane & 7) + ((lane >> 4) << 3)) * 128);

    float acc[4][8][4];
#pragma unroll
    for (int a = 0; a < 4; a++)
#pragma unroll
        for (int b = 0; b < 8; b++)
#pragma unroll
            for (int c = 0; c < 4; c++) acc[a][b][c] = 0.0f;

    // prologue: stages 0 (k-chunk 0) and 1 (k-chunk 1); srcA/srcB advance 128B per chunk
    ISSUE_STAGE(srcA, srcB, 0u);
    ISSUE_STAGE(srcA + 128, srcB + 128, (uint32_t)STAGE_BYTES);
    const char* srcAi = srcA + 256;           // next chunk to issue (k+2)
    const char* srcBi = srcB + 256;

    uint32_t fA[2][4][4], fB[2][4][4];
    uint32_t so = 0;                          // stage offset for chunk k
    uint32_t soIss = (uint32_t)SB2;           // stage offset for chunk k+2
    int kRem = KT - 2;                        // chunks still to issue

#pragma unroll 1
    for (int k = 0; k < KT; k++) {
        if (k < KT - 1) asm volatile("cp.async.wait_group 1;\n" ::: "memory");
        else            asm volatile("cp.async.wait_group 0;\n" ::: "memory");
        __syncthreads();

        uint32_t sA = smem_u32 + so;
        uint32_t sB = sA + STAGE_A;

        // prime kstep 0 fragments
        LDSM_FRAGS(fA[0], fB[0], sA, sB, 0u);

        LDSM_FRAGS(fA[1], fB[1], sA, sB, 2u);
        MMA_BURST(fA[0], fB[0]);

        LDSM_FRAGS(fA[0], fB[0], sA, sB, 4u);
        MMA_BURST(fA[1], fB[1]);

        LDSM_FRAGS(fA[1], fB[1], sA, sB, 6u);
        MMA_BURST(fA[0], fB[0]);

        if (kRem > 0) {
            ISSUE_STAGE(srcAi, srcBi, soIss);
            srcAi += 128; srcBi += 128; kRem--;
            soIss = (soIss == (uint32_t)SB2) ? 0u : soIss + STAGE_BYTES;
        }
        MMA_BURST(fA[1], fB[1]);

        so = (so == (uint32_t)SB2) ? 0u : so + STAGE_BYTES;
    }

    // -------- epilogue: acc -> smem (transpose to n-contiguous) --------
    __syncthreads();   // all compute done; stage smem now reusable
#pragma unroll
    for (int t4 = 0; t4 < 4; t4++) {
#pragma unroll
        for (int p = 0; p < 4; p++) {
            int r0 = wm * 64 + t4 * 16 + (lane >> 2);
            int c0 = wn * 64 + p * 16 + (lane & 3) * 2;
            *(float2*)&smemf[r0 * EPI_STRIDE + c0]            = make_float2(acc[t4][2 * p][0], acc[t4][2 * p][1]);
            *(float2*)&smemf[(r0 + 8) * EPI_STRIDE + c0]      = make_float2(acc[t4][2 * p][2], acc[t4][2 * p][3]);
            *(float2*)&smemf[r0 * EPI_STRIDE + c0 + 8]        = make_float2(acc[t4][2 * p + 1][0], acc[t4][2 * p + 1][1]);
            *(float2*)&smemf[(r0 + 8) * EPI_STRIDE + c0 + 8]  = make_float2(acc[t4][2 * p + 1][2], acc[t4][2 * p + 1][3]);
        }
    }
    __syncthreads();

    // -------- fused LSTM: gates -> h_t, c_t --------
    // c_prev is read-once (__ldcs) and outputs are never re-read (__stcs):
    // keep the GEMM operand set (g_A/g_W) resident in L2 for still-running blocks.
    int r = tid;                      // 0..127 (batch row within tile)
    int mrow = m0 + r;
    int hglob0 = nt * 32;             // this block's head range (BN/4 = 32 heads)
    const float* cpr = c_prev + (size_t)mrow * HSZ + hglob0;
    float* hout = out + (size_t)mrow * HSZ + hglob0;
    float* cout = out + (size_t)BATCH * HSZ + (size_t)mrow * HSZ + hglob0;
    const float* biasf = (const float*)(smem + BIAS_OFF);
#pragma unroll
    for (int g4 = 0; g4 < 8; g4++) {
        int hl = g4 * 4;                               // local head base
        float4 cp4 = __ldcs((const float4*)(cpr + hl));
        float cpv[4] = {cp4.x, cp4.y, cp4.z, cp4.w};
        float hv[4], cv[4];
#pragma unroll
        for (int j = 0; j < 4; j++) {
            const float* gt = &smemf[r * EPI_STRIDE + (hl + j) * 4];
            const float* bs = &biasf[(hl + j) * 4];
            float gf = gt[0] + bs[0];
            float gi = gt[1] + bs[1];
            float gc = gt[2] + bs[2];
            float go = gt[3] + bs[3];
            float f  = sigmoidf_(gf);
            float iv = sigmoidf_(gi);
            float ct = tanhf_(gc);
            float o  = sigmoidf_(go);
            float cn = fmaf(f, cpv[j], iv * ct);
            cv[j] = cn;
            hv[j] = o * tanhf_(cn);
        }
        __stcs((float4*)(hout + hl), make_float4(hv[0], hv[1], hv[2], hv[3]));
        __stcs((float4*)(cout + hl), make_float4(cv[0], cv[1], cv[2], cv[3]));
    }
}

// ---------------- launch ----------------
extern "C" void kernel_launch(void* const* d_in, const int* in_sizes, int n_in,
                              void* d_out, int out_size) {
    const float* x  = (const float*)d_in[0];
    const float* h  = (const float*)d_in[1];
    const float* c  = (const float*)d_in[2];
    const float* Wf = (const float*)d_in[3];
    const float* bf = (const float*)d_in[4];
    const float* Wi = (const float*)d_in[5];
    const float* bi = (const float*)d_in[6];
    const float* Wc = (const float*)d_in[7];
    const float* bc = (const float*)d_in[8];
    const float* Wo = (const float*)d_in[9];
    const float* bo = (const float*)d_in[10];
    float* out = (float*)d_out;

    conv_all_kernel<<<(W4CNT + A4CNT) / 256, 256>>>(x, h, Wf, Wi, Wc, Wo, bf, bi, bc, bo);

    static int smem_set = 0;
    if (!smem_set) {
        cudaFuncSetAttribute(lstm_gemm_kernel,
                             cudaFuncAttributeMaxDynamicSharedMemorySize, SMEM_TOTAL);
        smem_set = 1;
    }
    lstm_gemm_kernel<<<(BATCH / BM) * (NDIM / BN), NTHREADS, SMEM_TOTAL>>>(c, out);
}

// round 17
// speedup vs baseline: 1.0189x; 1.0189x over previous
#include <cuda_runtime.h>
#include <cuda_fp16.h>
#include <cstdint>

// ---------------- problem constants ----------------
#define HSZ   2048
#define BATCH 4096
#define KDIM  4096   // COMBINED
#define NDIM  8192   // 4H

// ---------------- fp16 scratch (device globals; no allocs) ----------------
__device__ __half g_A[(size_t)BATCH * KDIM];   // combined [B, C] fp16 (h_prev | x_t)
__device__ __half g_W[(size_t)NDIM * KDIM];    // weights, rows permuted n' = 4h + g
__device__ float  g_bias[NDIM];                // bias, permuted

__device__ __forceinline__ uint32_t smem_to_u32(const void* p) {
    uint32_t a;
    asm("{ .reg .u64 t; cvta.to.shared.u64 t, %1; cvt.u32.u64 %0, t; }" : "=r"(a) : "l"(p));
    return a;
}
// NON-volatile MMA: pure register op; lets ptxas interleave HMMA with ALU/LSU
__device__ __forceinline__ void mma16816(float* c, const uint32_t* a, const uint32_t* b) {
    asm("mma.sync.aligned.m16n8k16.row.col.f32.f16.f16.f32 "
        "{%0,%1,%2,%3}, {%4,%5,%6,%7}, {%8,%9}, {%0,%1,%2,%3};"
        : "+f"(c[0]), "+f"(c[1]), "+f"(c[2]), "+f"(c[3])
        : "r"(a[0]), "r"(a[1]), "r"(a[2]), "r"(a[3]), "r"(b[0]), "r"(b[1]));
}

// ---------------- pass 1: fused fp32 -> fp16 conversion (one kernel) ----------------
// Read-once fp32 sources use __ldcs (evict-first); separate kernel, cannot
// perturb the GEMM's register allocation.
#define W4CNT (NDIM * KDIM / 4)      // 8388608 float4-groups for W
#define A4CNT (BATCH * KDIM / 4)     // 4194304 float4-groups for A

__global__ void conv_all_kernel(const float* __restrict__ x,  const float* __restrict__ h,
                                const float* __restrict__ Wf, const float* __restrict__ Wi,
                                const float* __restrict__ Wc, const float* __restrict__ Wo,
                                const float* __restrict__ bf, const float* __restrict__ bi,
                                const float* __restrict__ bc, const float* __restrict__ bo) {
    int i4 = blockIdx.x * blockDim.x + threadIdx.x;
    if (i4 < W4CNT) {
        size_t e = (size_t)i4 << 2;
        int n = (int)(e >> 12), k = (int)(e & 4095);    // n' = 4h + g (permuted row)
        int g = n & 3, hh = n >> 2;
        const float* src = (g == 0) ? Wf : (g == 1) ? Wi : (g == 2) ? Wc : Wo;
        float4 v = __ldcs((const float4*)(src + (size_t)hh * KDIM + k));
        __half2* dst = (__half2*)(g_W + e);
        dst[0] = __floats2half2_rn(v.x, v.y);
        dst[1] = __floats2half2_rn(v.z, v.w);
        if (i4 < NDIM) {                                // bias: first NDIM threads
            int gg = i4 & 3, hb = i4 >> 2;
            const float* sb = (gg == 0) ? bf : (gg == 1) ? bi : (gg == 2) ? bc : bo;
            g_bias[i4] = sb[hb];
        }
    } else {
        int j = i4 - W4CNT;                             // A part
        int e = j << 2;
        int m = e >> 12, k = e & 4095;
        float4 v = (k < HSZ) ? __ldcs((const float4*)(h + (size_t)m * HSZ + k))
                             : __ldcs((const float4*)(x + (size_t)m * HSZ + (k - HSZ)));
        __half2* dst = (__half2*)(g_A + e);
        dst[0] = __floats2half2_rn(v.x, v.y);
        dst[1] = __floats2half2_rn(v.z, v.w);
    }
}

// ---------------- pass 2: mma.sync GEMM (R15 build, byte-identical) ----------------
// BM=BN=128, 128 threads (4 warps, 2x2 grid of 64x64 warp tiles), 2 CTAs/SM
#define BM 128
#define BN 128
#define KT 64                  // 4096 / 64
#define STAGE_A 16384          // 128 rows x 128B
#define STAGE_BYTES 32768      // A 16KB + B 16KB
#define SB2 (2 * STAGE_BYTES)
#define EPI_STRIDE 132         // floats per row (128 + 4 pad)
#define BIAS_OFF (3 * STAGE_BYTES)               // 98304
#define SMEM_TOTAL (BIAS_OFF + BN * 4)           // 98816 -> 2 CTAs/SM

#define NTHREADS 128

// hardware tanh (sm_75+): single MUFU op, max rel err ~2^-11
__device__ __forceinline__ float tanh_fast(float x) {
    float y; asm("tanh.approx.f32 %0, %1;" : "=f"(y) : "f"(x)); return y;
}
// sigmoid via tanh identity: 1 MUFU + 1 FMA (was EX2+RCP = 2 MUFU)
__device__ __forceinline__ float sigmoidf_(float x) {
    return fmaf(tanh_fast(0.5f * x), 0.5f, 0.5f);
}
__device__ __forceinline__ float tanhf_(float x) { return tanh_fast(x); }

// cp.async 16B with compile-time dst/src immediate offsets
#define CPI(da, sa, DI, SI) \
    asm volatile("cp.async.cg.shared.global [%0+%2], [%1+%3], 16;" \
                 :: "r"(da), "l"(sa), "n"(DI), "n"(SI) : "memory")

// ldmatrix x4 with compile-time immediate offset (row-tile stride 2048B)
#define LDSMI(rr, base, I) \
    asm volatile("ldmatrix.sync.aligned.m8n8.x4.shared.b16 {%0,%1,%2,%3}, [%4+%5];" \
                 : "=r"((rr)[0]), "=r"((rr)[1]), "=r"((rr)[2]), "=r"((rr)[3]) \
                 : "r"(base), "n"(I))

// prefetch one kstep's fragments: 2 address adds + 8 imm-offset ldsm
#define LDSM_FRAGS(dstA, dstB, sA, sB, kc) do {                    \
    uint32_t _aa = (sA) + a0 + ((((kc) + hi) ^ swz) << 4);         \
    uint32_t _bb = (sB) + b0 + ((((kc) + piece) ^ swz) << 4);      \
    LDSMI((dstA)[0], _aa, 0);    LDSMI((dstA)[1], _aa, 2048);      \
    LDSMI((dstA)[2], _aa, 4096); LDSMI((dstA)[3], _aa, 6144);      \
    LDSMI((dstB)[0], _bb, 0);    LDSMI((dstB)[1], _bb, 2048);      \
    LDSMI((dstB)[2], _bb, 4096); LDSMI((dstB)[3], _bb, 6144);      \
} while (0)

#define MMA_BURST(a, b) do {                                    \
    _Pragma("unroll")                                           \
    for (int _t = 0; _t < 4; _t++)                              \
        _Pragma("unroll")                                       \
        for (int _p = 0; _p < 4; _p++) {                        \
            mma16816(acc[_t][2 * _p],     (a)[_t], &(b)[_p][0]);\
            mma16816(acc[_t][2 * _p + 1], (a)[_t], &(b)[_p][2]);\
        }                                                       \
} while (0)

// one stage fill: 16 cp.async, all offsets immediate (16 rows * 8192B row-stride steps)
#define ISSUE_STAGE(saPtr, sbPtr, sOff) do {                                       \
    uint32_t _da = smem_u32 + (sOff) + dst0;                                       \
    uint32_t _db = _da + STAGE_A;                                                  \
    CPI(_da, (saPtr), 0, 0);            CPI(_da, (saPtr), 2048, 131072);           \
    CPI(_da, (saPtr), 4096, 262144);    CPI(_da, (saPtr), 6144, 393216);           \
    CPI(_da, (saPtr), 8192, 524288);    CPI(_da, (saPtr), 10240, 655360);          \
    CPI(_da, (saPtr), 12288, 786432);   CPI(_da, (saPtr), 14336, 917504);          \
    CPI(_db, (sbPtr), 0, 0);            CPI(_db, (sbPtr), 2048, 131072);           \
    CPI(_db, (sbPtr), 4096, 262144);    CPI(_db, (sbPtr), 6144, 393216);           \
    CPI(_db, (sbPtr), 8192, 524288);    CPI(_db, (sbPtr), 10240, 655360);          \
    CPI(_db, (sbPtr), 12288, 786432);   CPI(_db, (sbPtr), 14336, 917504);          \
    asm volatile("cp.async.commit_group;\n" ::: "memory");                         \
} while (0)

__global__ __launch_bounds__(NTHREADS, 2)
void lstm_gemm_kernel(const float* __restrict__ c_prev, float* __restrict__ out) {
    extern __shared__ char smem[];
    uint32_t smem_u32 = smem_to_u32(smem);
    float* smemf = (float*)smem;
    int tid = threadIdx.x;
    int lane = tid & 31, wid = tid >> 5;
    int wm = wid & 1, wn = wid >> 1;          // 2 x 2 warp grid, 64x64 warp tiles

    int mt = blockIdx.x & 31;                 // M-fastest: W panel stays hot in L2
    int nt = blockIdx.x >> 5;                 // 0..63
    int m0 = mt * BM, n0 = nt * BN;

    if (tid < BN / 4)
        ((float4*)(smem + BIAS_OFF))[tid] = ((const float4*)(g_bias + n0))[tid];

    // ---- cp.async addressing: incremental byte pointers, imm offsets inside stage ----
    uint32_t srcOff0b = (uint32_t)(((tid >> 3) * KDIM + (tid & 7) * 8) * 2);       // bytes
    uint32_t dst0     = (uint32_t)((tid >> 3) * 128 + (((tid & 7) ^ ((tid >> 3) & 7)) << 4));
    const char* srcA = (const char*)(g_A + (size_t)m0 * KDIM) + srcOff0b;
    const char* srcB = (const char*)(g_W + (size_t)n0 * KDIM) + srcOff0b;

    // ---- ldmatrix addressing ----
    uint32_t swz = (uint32_t)(lane & 7);
    uint32_t hi = (uint32_t)(lane >> 4);            // A k-half select
    uint32_t piece = (uint32_t)((lane >> 3) & 1);   // B k-half select
    uint32_t a0 = (uint32_t)((wm * 64 + (lane & 15)) * 128);
    uint32_t b0 = (uint32_t)((wn * 64 + (lane & 7) + ((lane >> 4) << 3)) * 128);

    float acc[4][8][4];
#pragma unroll
    for (int a = 0; a < 4; a++)
#pragma unroll
        for (int b = 0; b < 8; b++)
#pragma unroll
            for (int c = 0; c < 4; c++) acc[a][b][c] = 0.0f;

    // prologue: stages 0 (k-chunk 0) and 1 (k-chunk 1); srcA/srcB advance 128B per chunk
    ISSUE_STAGE(srcA, srcB, 0u);
    ISSUE_STAGE(srcA + 128, srcB + 128, (uint32_t)STAGE_BYTES);
    const char* srcAi = srcA + 256;           // next chunk to issue (k+2)
    const char* srcBi = srcB + 256;

    uint32_t fA[2][4][4], fB[2][4][4];
    uint32_t so = 0;                          // stage offset for chunk k
    uint32_t soIss = (uint32_t)SB2;           // stage offset for chunk k+2
    int kRem = KT - 2;                        // chunks still to issue

#pragma unroll 1
    for (int k = 0; k < KT; k++) {
        if (k < KT - 1) asm volatile("cp.async.wait_group 1;\n" ::: "memory");
        else            asm volatile("cp.async.wait_group 0;\n" ::: "memory");
        __syncthreads();

        uint32_t sA = smem_u32 + so;
        uint32_t sB = sA + STAGE_A;

        // prime kstep 0 fragments
        LDSM_FRAGS(fA[0], fB[0], sA, sB, 0u);

        LDSM_FRAGS(fA[1], fB[1], sA, sB, 2u);
        MMA_BURST(fA[0], fB[0]);

        LDSM_FRAGS(fA[0], fB[0], sA, sB, 4u);
        MMA_BURST(fA[1], fB[1]);

        LDSM_FRAGS(fA[1], fB[1], sA, sB, 6u);
        MMA_BURST(fA[0], fB[0]);

        if (kRem > 0) {
            ISSUE_STAGE(srcAi, srcBi, soIss);
            srcAi += 128; srcBi += 128; kRem--;
            soIss = (soIss == (uint32_t)SB2) ? 0u : soIss + STAGE_BYTES;
        }
        MMA_BURST(fA[1], fB[1]);

        so = (so == (uint32_t)SB2) ? 0u : so + STAGE_BYTES;
    }

    // -------- epilogue: acc -> smem (transpose to n-contiguous) --------
    __syncthreads();   // all compute done; stage smem now reusable
#pragma unroll
    for (int t4 = 0; t4 < 4; t4++) {
#pragma unroll
        for (int p = 0; p < 4; p++) {
            int r0 = wm * 64 + t4 * 16 + (lane >> 2);
            int c0 = wn * 64 + p * 16 + (lane & 3) * 2;
            *(float2*)&smemf[r0 * EPI_STRIDE + c0]            = make_float2(acc[t4][2 * p][0], acc[t4][2 * p][1]);
            *(float2*)&smemf[(r0 + 8) * EPI_STRIDE + c0]      = make_float2(acc[t4][2 * p][2], acc[t4][2 * p][3]);
            *(float2*)&smemf[r0 * EPI_STRIDE + c0 + 8]        = make_float2(acc[t4][2 * p + 1][0], acc[t4][2 * p + 1][1]);
            *(float2*)&smemf[(r0 + 8) * EPI_STRIDE + c0 + 8]  = make_float2(acc[t4][2 * p + 1][2], acc[t4][2 * p + 1][3]);
        }
    }
    __syncthreads();

    // -------- fused LSTM: gates -> h_t, c_t --------
    int r = tid;                      // 0..127 (batch row within tile)
    int mrow = m0 + r;
    int hglob0 = nt * 32;             // this block's head range (BN/4 = 32 heads)
    const float* cpr = c_prev + (size_t)mrow * HSZ + hglob0;
    float* hout = out + (size_t)mrow * HSZ + hglob0;
    float* cout = out + (size_t)BATCH * HSZ + (size_t)mrow * HSZ + hglob0;
    const float* biasf = (const float*)(smem + BIAS_OFF);
#pragma unroll
    for (int g4 = 0; g4 < 8; g4++) {
        int hl = g4 * 4;                               // local head base
        float4 cp4 = *(const float4*)(cpr + hl);
        float cpv[4] = {cp4.x, cp4.y, cp4.z, cp4.w};
        float hv[4], cv[4];
#pragma unroll
        for (int j = 0; j < 4; j++) {
            const float* gt = &smemf[r * EPI_STRIDE + (hl + j) * 4];
            const float* bs = &biasf[(hl + j) * 4];
            float gf = gt[0] + bs[0];
            float gi = gt[1] + bs[1];
            float gc = gt[2] + bs[2];
            float go = gt[3] + bs[3];
            float f  = sigmoidf_(gf);
            float iv = sigmoidf_(gi);
            float ct = tanhf_(gc);
            float o  = sigmoidf_(go);
            float cn = fmaf(f, cpv[j], iv * ct);
            cv[j] = cn;
            hv[j] = o * tanhf_(cn);
        }
        *(float4*)(hout + hl) = make_float4(hv[0], hv[1], hv[2], hv[3]);
        *(float4*)(cout + hl) = make_float4(cv[0], cv[1], cv[2], cv[3]);
    }
}

// ---------------- launch ----------------
extern "C" void kernel_launch(void* const* d_in, const int* in_sizes, int n_in,
                              void* d_out, int out_size) {
    const float* x  = (const float*)d_in[0];
    const float* h  = (const float*)d_in[1];
    const float* c  = (const float*)d_in[2];
    const float* Wf = (const float*)d_in[3];
    const float* bf = (const float*)d_in[4];
    const float* Wi = (const float*)d_in[5];
    const float* bi = (const float*)d_in[6];
    const float* Wc = (const float*)d_in[7];
    const float* bc = (const float*)d_in[8];
    const float* Wo = (const float*)d_in[9];
    const float* bo = (const float*)d_in[10];
    float* out = (float*)d_out;

    conv_all_kernel<<<(W4CNT + A4CNT) / 256, 256>>>(x, h, Wf, Wi, Wc, Wo, bf, bi, bc, bo);

    static int smem_set = 0;
    if (!smem_set) {
        cudaFuncSetAttribute(lstm_gemm_kernel,
                             cudaFuncAttributeMaxDynamicSharedMemorySize, SMEM_TOTAL);
        smem_set = 1;
    }
    lstm_gemm_kernel<<<(BATCH / BM) * (NDIM / BN), NTHREADS, SMEM_TOTAL>>>(c, out);
}